// round 1
// baseline (speedup 1.0000x reference)
#include <cuda_runtime.h>
#include <cuda_bf16.h>
#include <stdint.h>

// Problem constants
#define Bp    4
#define Np    50000
#define Ep    800000
#define FIN   128
#define FOUT  128
#define Mrows (Bp * Np)            // 200000 rows for the GEMM

// ---------------------------------------------------------------------------
// Device-global scratch (no cudaMalloc allowed)
// ---------------------------------------------------------------------------
__device__ float g_h[(size_t)Bp * Np * FOUT];   // 102.4 MB: h = x @ W^T
__device__ int   g_counts[Np + 1];
__device__ int   g_offsets[Np + 1];
__device__ int   g_cursor[Np];
__device__ int   g_col[Ep];
__device__ float g_val[Ep];
__device__ int   g_idx64;                        // 1 if edge indices are int64

// ---------------------------------------------------------------------------
// Detect int32 vs int64 edge indices.
// If int64 (values < 2^31, non-negative), every odd int32 word is 0.
// ---------------------------------------------------------------------------
__global__ void detect_kernel(const int* __restrict__ er) {
    __shared__ int any_nonzero;
    if (threadIdx.x == 0) any_nonzero = 0;
    __syncthreads();
    for (int i = threadIdx.x; i < 2048; i += blockDim.x) {
        if (er[2 * i + 1] != 0) any_nonzero = 1;
    }
    __syncthreads();
    if (threadIdx.x == 0) g_idx64 = any_nonzero ? 0 : 1;
}

// ---------------------------------------------------------------------------
// Zero the row-degree histogram
// ---------------------------------------------------------------------------
__global__ void zero_counts_kernel() {
    int i = blockIdx.x * blockDim.x + threadIdx.x;
    if (i <= Np) g_counts[i] = 0;
}

// ---------------------------------------------------------------------------
// Histogram of edge_row
// ---------------------------------------------------------------------------
__global__ void hist_kernel(const int* __restrict__ er) {
    const int idx64 = g_idx64;
    int e = blockIdx.x * blockDim.x + threadIdx.x;
    if (e >= Ep) return;
    int r = idx64 ? er[2 * e] : er[e];
    atomicAdd(&g_counts[r], 1);
}

// ---------------------------------------------------------------------------
// Single-block exclusive scan over counts -> offsets (and cursor copy).
// shfl warp scan + cross-warp scan; 49 chunks of 1024.
// ---------------------------------------------------------------------------
__global__ void scan_kernel() {
    __shared__ int warpsum[32];
    __shared__ int s_run;
    const int t    = threadIdx.x;
    const int lane = t & 31;
    const int w    = t >> 5;
    if (t == 0) s_run = 0;
    __syncthreads();

    for (int base = 0; base < Np; base += 1024) {
        int i = base + t;
        int v = (i < Np) ? g_counts[i] : 0;

        // inclusive warp scan
        int x = v;
        #pragma unroll
        for (int off = 1; off < 32; off <<= 1) {
            int y = __shfl_up_sync(0xFFFFFFFFu, x, off);
            if (lane >= off) x += y;
        }
        if (lane == 31) warpsum[w] = x;
        __syncthreads();
        if (w == 0) {
            int s = warpsum[lane];
            #pragma unroll
            for (int off = 1; off < 32; off <<= 1) {
                int y = __shfl_up_sync(0xFFFFFFFFu, s, off);
                if (lane >= off) s += y;
            }
            warpsum[lane] = s;   // inclusive across warps
        }
        __syncthreads();

        int incl  = x + (w > 0 ? warpsum[w - 1] : 0);
        int run0  = s_run;
        int excl  = run0 + incl - v;
        if (i < Np) {
            g_offsets[i] = excl;
            g_cursor[i]  = excl;
        }
        int total = warpsum[31];
        __syncthreads();
        if (t == 0) s_run = run0 + total;
        __syncthreads();
    }
    if (t == 0) g_offsets[Np] = s_run;
}

// ---------------------------------------------------------------------------
// Scatter edges into CSR order
// ---------------------------------------------------------------------------
__global__ void scatter_kernel(const int* __restrict__ er,
                               const int* __restrict__ ec,
                               const float* __restrict__ ev) {
    const int idx64 = g_idx64;
    int e = blockIdx.x * blockDim.x + threadIdx.x;
    if (e >= Ep) return;
    int r = idx64 ? er[2 * e] : er[e];
    int c = idx64 ? ec[2 * e] : ec[e];
    int p = atomicAdd(&g_cursor[r], 1);
    g_col[p] = c;
    g_val[p] = ev[e];
}

// ---------------------------------------------------------------------------
// GEMM: h[m][o] = sum_k x[m][k] * W[o][k]     (M=200000, K=128, Nout=128)
// BM=128, BN=128, BK=16, 256 threads, 8x8 microtile. 16 KB smem.
// ---------------------------------------------------------------------------
__global__ __launch_bounds__(256, 2)
void gemm_kernel(const float* __restrict__ A, const float* __restrict__ W,
                 float* __restrict__ C) {
    __shared__ float As[16][128];
    __shared__ float Bs[16][128];

    const int tid = threadIdx.x;
    const int tx  = tid & 15;          // 0..15 -> N
    const int ty  = tid >> 4;          // 0..15 -> M
    const long blockM = (long)blockIdx.x * 128;

    float acc[8][8];
    #pragma unroll
    for (int i = 0; i < 8; i++)
        #pragma unroll
        for (int j = 0; j < 8; j++) acc[i][j] = 0.0f;

    for (int k0 = 0; k0 < 128; k0 += 16) {
        // Load A tile (128 rows x 16 k) as float4, transpose into As[k][m]
        #pragma unroll
        for (int v = 0; v < 2; v++) {
            int id  = tid + v * 256;       // 0..511
            int row = id >> 2;
            int kq  = id & 3;
            long gr = blockM + row;
            float4 t = (gr < Mrows)
                ? __ldg(&((const float4*)A)[gr * 32 + (k0 >> 2) + kq])
                : make_float4(0.f, 0.f, 0.f, 0.f);
            As[kq * 4 + 0][row] = t.x;
            As[kq * 4 + 1][row] = t.y;
            As[kq * 4 + 2][row] = t.z;
            As[kq * 4 + 3][row] = t.w;
        }
        // Load B tile: W[n][k0..k0+15] -> Bs[k][n]
        #pragma unroll
        for (int v = 0; v < 2; v++) {
            int id = tid + v * 256;
            int n  = id >> 2;
            int kq = id & 3;
            float4 t = __ldg(&((const float4*)W)[n * 32 + (k0 >> 2) + kq]);
            Bs[kq * 4 + 0][n] = t.x;
            Bs[kq * 4 + 1][n] = t.y;
            Bs[kq * 4 + 2][n] = t.z;
            Bs[kq * 4 + 3][n] = t.w;
        }
        __syncthreads();

        #pragma unroll
        for (int k = 0; k < 16; k++) {
            float a[8], b[8];
            float4 a0 = *(const float4*)&As[k][ty * 8];
            float4 a1 = *(const float4*)&As[k][ty * 8 + 4];
            float4 b0 = *(const float4*)&Bs[k][tx * 8];
            float4 b1 = *(const float4*)&Bs[k][tx * 8 + 4];
            a[0]=a0.x; a[1]=a0.y; a[2]=a0.z; a[3]=a0.w;
            a[4]=a1.x; a[5]=a1.y; a[6]=a1.z; a[7]=a1.w;
            b[0]=b0.x; b[1]=b0.y; b[2]=b0.z; b[3]=b0.w;
            b[4]=b1.x; b[5]=b1.y; b[6]=b1.z; b[7]=b1.w;
            #pragma unroll
            for (int i = 0; i < 8; i++)
                #pragma unroll
                for (int j = 0; j < 8; j++)
                    acc[i][j] += a[i] * b[j];
        }
        __syncthreads();
    }

    #pragma unroll
    for (int i = 0; i < 8; i++) {
        long gr = blockM + ty * 8 + i;
        if (gr < Mrows) {
            float4* crow = (float4*)(C + gr * 128);
            crow[tx * 2 + 0] = make_float4(acc[i][0], acc[i][1], acc[i][2], acc[i][3]);
            crow[tx * 2 + 1] = make_float4(acc[i][4], acc[i][5], acc[i][6], acc[i][7]);
        }
    }
}

// ---------------------------------------------------------------------------
// SpMM: out[b][r][:] = sum_{e in row r} val[e] * h[b][col[e]][:]
// One warp per (row, batch). Lane handles a float4 (128 = 32 lanes * 4).
// ---------------------------------------------------------------------------
__global__ __launch_bounds__(256)
void spmm_kernel(float* __restrict__ out) {
    const int warp = threadIdx.x >> 5;
    const int lane = threadIdx.x & 31;
    const int r = blockIdx.x * 8 + warp;
    const int b = blockIdx.y;
    if (r >= Np) return;

    const float4* __restrict__ hb =
        (const float4*)(g_h + (size_t)b * Np * FOUT);
    const int* __restrict__ cols = g_col;
    const float* __restrict__ vals = g_val;

    int s = g_offsets[r];
    int e = g_offsets[r + 1];

    float4 acc = make_float4(0.f, 0.f, 0.f, 0.f);
    int i = s;
    // 2-way unrolled gather for MLP
    for (; i + 2 <= e; i += 2) {
        int   c0 = __ldg(&cols[i]);
        int   c1 = __ldg(&cols[i + 1]);
        float v0 = __ldg(&vals[i]);
        float v1 = __ldg(&vals[i + 1]);
        float4 t0 = __ldg(&hb[(size_t)c0 * 32 + lane]);
        float4 t1 = __ldg(&hb[(size_t)c1 * 32 + lane]);
        acc.x += v0 * t0.x + v1 * t1.x;
        acc.y += v0 * t0.y + v1 * t1.y;
        acc.z += v0 * t0.z + v1 * t1.z;
        acc.w += v0 * t0.w + v1 * t1.w;
    }
    if (i < e) {
        int   c0 = __ldg(&cols[i]);
        float v0 = __ldg(&vals[i]);
        float4 t0 = __ldg(&hb[(size_t)c0 * 32 + lane]);
        acc.x += v0 * t0.x;
        acc.y += v0 * t0.y;
        acc.z += v0 * t0.z;
        acc.w += v0 * t0.w;
    }
    float4* orow = (float4*)(out + ((size_t)b * Np + r) * FOUT);
    orow[lane] = acc;
}

// ---------------------------------------------------------------------------
// Launch
// ---------------------------------------------------------------------------
extern "C" void kernel_launch(void* const* d_in, const int* in_sizes, int n_in,
                              void* d_out, int out_size) {
    const float* x  = (const float*)d_in[0];   // [4,50000,128]
    const float* W  = (const float*)d_in[1];   // [128,128]
    const int*   er = (const int*)d_in[2];     // edge_row (int32 or int64)
    const int*   ec = (const int*)d_in[3];     // edge_col
    const float* ev = (const float*)d_in[4];   // edge_vals
    float* out = (float*)d_out;

    float* h;
    cudaGetSymbolAddress((void**)&h, g_h);

    // 1) dense projection h = x @ W^T
    gemm_kernel<<<(Mrows + 127) / 128, 256>>>(x, W, h);

    // 2) CSR build
    detect_kernel<<<1, 256>>>(er);
    zero_counts_kernel<<<(Np + 256) / 256, 256>>>();
    hist_kernel<<<(Ep + 255) / 256, 256>>>(er);
    scan_kernel<<<1, 1024>>>();
    scatter_kernel<<<(Ep + 255) / 256, 256>>>(er, ec, ev);

    // 3) SpMM segment sum
    dim3 g((Np + 7) / 8, Bp);
    spmm_kernel<<<g, 256>>>(out);
}